// round 1
// baseline (speedup 1.0000x reference)
#include <cuda_runtime.h>
#include <math.h>

#define NB     2
#define SQ     2048
#define HIDDEN 1024
#define NHEAD  16
#define HDIM   64
#define SKVLEN 2048
#define TKV    (SKVLEN + SQ)   // 4096 total keys

// Scratch for projected Q (pre-scaled by 1/64), K, V in [B, NH, S, HD] layout.
__device__ float g_q[NB * NHEAD * SQ * HDIM];
__device__ float g_k[NB * NHEAD * SQ * HDIM];
__device__ float g_v[NB * NHEAD * SQ * HDIM];

// ---------------------------------------------------------------------------
// Kernel 1: fused QKV projection.  y = x @ W^T + b  (NT GEMM, both K-contig)
// grid = (M/64, N/64, 3);  block = 256 (16x16, 4x4 per thread), K-tile = 16
// z = 0: Q (scaled by scale^2 = 1/64), 1: K, 2: V.
// Output written directly in [B, NH, S, HD] layout (n-tile == one head).
// ---------------------------------------------------------------------------
__global__ __launch_bounds__(256)
void qkv_kernel(const float* __restrict__ x,
                const float* __restrict__ Wq, const float* __restrict__ bq,
                const float* __restrict__ Wk, const float* __restrict__ bk,
                const float* __restrict__ Wv, const float* __restrict__ bv)
{
    __shared__ float As[16][68];   // [k][m], padded
    __shared__ float Bs[16][68];   // [k][n], padded

    const int z = blockIdx.z;
    const float* __restrict__ W    = (z == 0) ? Wq : (z == 1) ? Wk : Wv;
    const float* __restrict__ bias = (z == 0) ? bq : (z == 1) ? bk : bv;
    float* __restrict__ out        = (z == 0) ? g_q : (z == 1) ? g_k : g_v;
    const float sc = (z == 0) ? (1.0f / 64.0f) : 1.0f;

    const int m0 = blockIdx.x * 64;
    const int n0 = blockIdx.y * 64;
    const int t  = threadIdx.x;
    const int ty = t >> 4, tx = t & 15;
    const int lrow = t >> 2;          // 0..63
    const int lk4  = (t & 3) * 4;     // 0,4,8,12

    const float* aptr = x + (m0 + lrow) * HIDDEN + lk4;
    const float* bptr = W + (n0 + lrow) * HIDDEN + lk4;

    float acc[4][4] = {};

    for (int k0 = 0; k0 < HIDDEN; k0 += 16) {
        float4 av  = *(const float4*)(aptr + k0);
        float4 bv4 = *(const float4*)(bptr + k0);
        __syncthreads();
        As[lk4 + 0][lrow] = av.x;  As[lk4 + 1][lrow] = av.y;
        As[lk4 + 2][lrow] = av.z;  As[lk4 + 3][lrow] = av.w;
        Bs[lk4 + 0][lrow] = bv4.x; Bs[lk4 + 1][lrow] = bv4.y;
        Bs[lk4 + 2][lrow] = bv4.z; Bs[lk4 + 3][lrow] = bv4.w;
        __syncthreads();

        #pragma unroll
        for (int kk = 0; kk < 16; kk++) {
            float4 a = *(const float4*)&As[kk][ty * 4];
            float4 b = *(const float4*)&Bs[kk][tx * 4];
            float aa[4] = {a.x, a.y, a.z, a.w};
            float bb[4] = {b.x, b.y, b.z, b.w};
            #pragma unroll
            for (int i = 0; i < 4; i++)
                #pragma unroll
                for (int j = 0; j < 4; j++)
                    acc[i][j] = fmaf(aa[i], bb[j], acc[i][j]);
        }
    }

    const int h = blockIdx.y;   // n-tile of 64 == exactly one head
    #pragma unroll
    for (int i = 0; i < 4; i++) {
        int m = m0 + ty * 4 + i;
        int bb = m >> 11;
        int srow = m & (SQ - 1);
        float4 o;
        o.x = (acc[i][0] + bias[n0 + tx * 4 + 0]) * sc;
        o.y = (acc[i][1] + bias[n0 + tx * 4 + 1]) * sc;
        o.z = (acc[i][2] + bias[n0 + tx * 4 + 2]) * sc;
        o.w = (acc[i][3] + bias[n0 + tx * 4 + 3]) * sc;
        *(float4*)&out[((bb * NHEAD + h) * SQ + srow) * HDIM + tx * 4] = o;
    }
}

// ---------------------------------------------------------------------------
// Kernel 2: flash attention over concat(kv_weight*kvs, projected K/V).
// grid = (SQ/64, B*NH);  block = 256 (16x16, 4x4 per thread)
// smem: Qt[d][q] | KP (Kt[d][j] then Pt[j][q], live ranges disjoint) | Vs[j][d]
// ---------------------------------------------------------------------------
#define SMSTR 68
#define ATTN_SMEM (3 * 64 * SMSTR * (int)sizeof(float))

__global__ __launch_bounds__(256)
void attn_kernel(const float* __restrict__ kvs,
                 const float* __restrict__ kvw_p,
                 float* __restrict__ out)
{
    extern __shared__ float sm[];
    float* Qt = sm;                    // [64][68] d-major
    float* KP = sm + 64 * SMSTR;       // Kt [d][j]  /  Pt [j][q]
    float* Vs = sm + 2 * 64 * SMSTR;   // [j][d]

    const int t  = threadIdx.x;
    const int ty = t >> 4, tx = t & 15;
    const int lrow = t >> 2;           // 0..63
    const int lq4  = (t & 3) * 4;      // 0,4,8,12
    const int q0 = blockIdx.x * 64;
    const int bh = blockIdx.y;         // b*NH + h
    const int bb = bh >> 4, h = bh & 15;
    const float kvw = kvw_p[0];

    // Load Q tile transposed: Qt[d][q]
    {
        const float* qptr = g_q + (bh * SQ + q0 + lrow) * HDIM;
        #pragma unroll
        for (int u = 0; u < 4; u++) {
            int d0 = lq4 + 16 * u;
            float4 v = *(const float4*)(qptr + d0);
            Qt[(d0 + 0) * SMSTR + lrow] = v.x;
            Qt[(d0 + 1) * SMSTR + lrow] = v.y;
            Qt[(d0 + 2) * SMSTR + lrow] = v.z;
            Qt[(d0 + 3) * SMSTR + lrow] = v.w;
        }
    }

    float O[4][4] = {};
    float mrun[4] = {-INFINITY, -INFINITY, -INFINITY, -INFINITY};
    float lrun[4] = {};

    const float* kbase0 = kvs + (size_t)bh * SKVLEN * HDIM;
    const float* vbase0 = kvs + ((size_t)NB * NHEAD + bh) * SKVLEN * HDIM;
    const float* kbase1 = g_k + bh * SQ * HDIM;
    const float* vbase1 = g_v + bh * SQ * HDIM;

    for (int kt = 0; kt < TKV / 64; kt++) {
        int jg = kt * 64 + lrow;
        const float *kp, *vp;
        float w;
        if (jg < SKVLEN) { kp = kbase0 + jg * HDIM; vp = vbase0 + jg * HDIM; w = kvw; }
        else { int js = jg - SKVLEN; kp = kbase1 + js * HDIM; vp = vbase1 + js * HDIM; w = 1.0f; }

        __syncthreads();   // previous GEMM2 done reading KP/Vs
        #pragma unroll
        for (int u = 0; u < 4; u++) {
            int d0 = lq4 + 16 * u;
            float4 kv4 = *(const float4*)(kp + d0);
            KP[(d0 + 0) * SMSTR + lrow] = kv4.x * w;
            KP[(d0 + 1) * SMSTR + lrow] = kv4.y * w;
            KP[(d0 + 2) * SMSTR + lrow] = kv4.z * w;
            KP[(d0 + 3) * SMSTR + lrow] = kv4.w * w;
            float4 vv4 = *(const float4*)(vp + d0);
            vv4.x *= w; vv4.y *= w; vv4.z *= w; vv4.w *= w;
            *(float4*)&Vs[lrow * SMSTR + d0] = vv4;
        }
        __syncthreads();

        // GEMM1: S = Q K^T  (inner dim = HD = 64)
        float s4[4][4] = {};
        #pragma unroll 8
        for (int d = 0; d < 64; d++) {
            float4 a = *(const float4*)&Qt[d * SMSTR + ty * 4];
            float4 b = *(const float4*)&KP[d * SMSTR + tx * 4];
            float aa[4] = {a.x, a.y, a.z, a.w};
            float bbv[4] = {b.x, b.y, b.z, b.w};
            #pragma unroll
            for (int i = 0; i < 4; i++)
                #pragma unroll
                for (int j = 0; j < 4; j++)
                    s4[i][j] = fmaf(aa[i], bbv[j], s4[i][j]);
        }

        // Online softmax (row = q; reduce across the 16 tx lanes)
        float al[4];
        #pragma unroll
        for (int i = 0; i < 4; i++) {
            float mv = fmaxf(fmaxf(s4[i][0], s4[i][1]), fmaxf(s4[i][2], s4[i][3]));
            mv = fmaxf(mv, __shfl_xor_sync(0xffffffffu, mv, 1, 16));
            mv = fmaxf(mv, __shfl_xor_sync(0xffffffffu, mv, 2, 16));
            mv = fmaxf(mv, __shfl_xor_sync(0xffffffffu, mv, 4, 16));
            mv = fmaxf(mv, __shfl_xor_sync(0xffffffffu, mv, 8, 16));
            float mn = fmaxf(mrun[i], mv);
            al[i] = __expf(mrun[i] - mn);
            mrun[i] = mn;
            float s = 0.0f;
            #pragma unroll
            for (int j = 0; j < 4; j++) {
                s4[i][j] = __expf(s4[i][j] - mn);
                s += s4[i][j];
            }
            s += __shfl_xor_sync(0xffffffffu, s, 1, 16);
            s += __shfl_xor_sync(0xffffffffu, s, 2, 16);
            s += __shfl_xor_sync(0xffffffffu, s, 4, 16);
            s += __shfl_xor_sync(0xffffffffu, s, 8, 16);
            lrun[i] = lrun[i] * al[i] + s;
        }

        __syncthreads();   // GEMM1 reads of KP complete before overwrite
        // Write Pt[j][q] over KP; rescale O
        #pragma unroll
        for (int i = 0; i < 4; i++) {
            #pragma unroll
            for (int j = 0; j < 4; j++) {
                KP[(tx * 4 + j) * SMSTR + ty * 4 + i] = s4[i][j];
                O[i][j] *= al[i];
            }
        }
        __syncthreads();

        // GEMM2: O += P V   (inner dim = 64 keys)
        #pragma unroll 8
        for (int j = 0; j < 64; j++) {
            float4 a = *(const float4*)&KP[j * SMSTR + ty * 4];
            float4 b = *(const float4*)&Vs[j * SMSTR + tx * 4];
            float aa[4] = {a.x, a.y, a.z, a.w};
            float bbv[4] = {b.x, b.y, b.z, b.w};
            #pragma unroll
            for (int i = 0; i < 4; i++)
                #pragma unroll
                for (int jj = 0; jj < 4; jj++)
                    O[i][jj] = fmaf(aa[i], bbv[jj], O[i][jj]);
        }
    }

    // Epilogue: normalize, write ctx[b, s, h*64 + d]
    #pragma unroll
    for (int i = 0; i < 4; i++) {
        float inv = 1.0f / lrun[i];
        float4 o;
        o.x = O[i][0] * inv; o.y = O[i][1] * inv;
        o.z = O[i][2] * inv; o.w = O[i][3] * inv;
        *(float4*)&out[((size_t)(bb * SQ + q0 + ty * 4 + i)) * HIDDEN + h * HDIM + tx * 4] = o;
    }
}

// ---------------------------------------------------------------------------
extern "C" void kernel_launch(void* const* d_in, const int* in_sizes, int n_in,
                              void* d_out, int out_size)
{
    const float* x    = (const float*)d_in[0];
    const float* kvs  = (const float*)d_in[1];
    const float* Wq   = (const float*)d_in[2];
    const float* bq   = (const float*)d_in[3];
    const float* Wk   = (const float*)d_in[4];
    const float* bk   = (const float*)d_in[5];
    const float* Wv   = (const float*)d_in[6];
    const float* bv   = (const float*)d_in[7];
    const float* kvw  = (const float*)d_in[8];
    float* out = (float*)d_out;

    dim3 g1(NB * SQ / 64, HIDDEN / 64, 3);
    qkv_kernel<<<g1, 256>>>(x, Wq, bq, Wk, bk, Wv, bv);

    cudaFuncSetAttribute(attn_kernel, cudaFuncAttributeMaxDynamicSharedMemorySize,
                         ATTN_SMEM);
    dim3 g2(SQ / 64, NB * NHEAD);
    attn_kernel<<<g2, 256, ATTN_SMEM>>>(kvs, kvw, out);
}

// round 2
// speedup vs baseline: 1.4823x; 1.4823x over previous
#include <cuda_runtime.h>
#include <math.h>

#define NB     2
#define SQ     2048
#define HIDDEN 1024
#define NHEAD  16
#define HDIM   64
#define SKVLEN 2048
#define TKV    (SKVLEN + SQ)   // 4096 total keys

// Scratch for projected Q (pre-scaled by 1/64), K, V in [B, NH, S, HD] layout.
__device__ float g_q[NB * NHEAD * SQ * HDIM];
__device__ float g_k[NB * NHEAD * SQ * HDIM];
__device__ float g_v[NB * NHEAD * SQ * HDIM];

// ---------------------------------------------------------------------------
// Kernel 1: fused QKV projection (fp32 SIMT; at FFMA roofline already).
// ---------------------------------------------------------------------------
__global__ __launch_bounds__(256)
void qkv_kernel(const float* __restrict__ x,
                const float* __restrict__ Wq, const float* __restrict__ bq,
                const float* __restrict__ Wk, const float* __restrict__ bk,
                const float* __restrict__ Wv, const float* __restrict__ bv)
{
    __shared__ float As[16][68];
    __shared__ float Bs[16][68];

    const int z = blockIdx.z;
    const float* __restrict__ W    = (z == 0) ? Wq : (z == 1) ? Wk : Wv;
    const float* __restrict__ bias = (z == 0) ? bq : (z == 1) ? bk : bv;
    float* __restrict__ out        = (z == 0) ? g_q : (z == 1) ? g_k : g_v;
    const float sc = (z == 0) ? (1.0f / 64.0f) : 1.0f;

    const int m0 = blockIdx.x * 64;
    const int n0 = blockIdx.y * 64;
    const int t  = threadIdx.x;
    const int ty = t >> 4, tx = t & 15;
    const int lrow = t >> 2;
    const int lk4  = (t & 3) * 4;

    const float* aptr = x + (m0 + lrow) * HIDDEN + lk4;
    const float* bptr = W + (n0 + lrow) * HIDDEN + lk4;

    float acc[4][4] = {};

    for (int k0 = 0; k0 < HIDDEN; k0 += 16) {
        float4 av  = *(const float4*)(aptr + k0);
        float4 bv4 = *(const float4*)(bptr + k0);
        __syncthreads();
        As[lk4 + 0][lrow] = av.x;  As[lk4 + 1][lrow] = av.y;
        As[lk4 + 2][lrow] = av.z;  As[lk4 + 3][lrow] = av.w;
        Bs[lk4 + 0][lrow] = bv4.x; Bs[lk4 + 1][lrow] = bv4.y;
        Bs[lk4 + 2][lrow] = bv4.z; Bs[lk4 + 3][lrow] = bv4.w;
        __syncthreads();

        #pragma unroll
        for (int kk = 0; kk < 16; kk++) {
            float4 a = *(const float4*)&As[kk][ty * 4];
            float4 b = *(const float4*)&Bs[kk][tx * 4];
            float aa[4] = {a.x, a.y, a.z, a.w};
            float bb[4] = {b.x, b.y, b.z, b.w};
            #pragma unroll
            for (int i = 0; i < 4; i++)
                #pragma unroll
                for (int j = 0; j < 4; j++)
                    acc[i][j] = fmaf(aa[i], bb[j], acc[i][j]);
        }
    }

    const int h = blockIdx.y;
    #pragma unroll
    for (int i = 0; i < 4; i++) {
        int m = m0 + ty * 4 + i;
        int bb = m >> 11;
        int srow = m & (SQ - 1);
        float4 o;
        o.x = (acc[i][0] + bias[n0 + tx * 4 + 0]) * sc;
        o.y = (acc[i][1] + bias[n0 + tx * 4 + 1]) * sc;
        o.z = (acc[i][2] + bias[n0 + tx * 4 + 2]) * sc;
        o.w = (acc[i][3] + bias[n0 + tx * 4 + 3]) * sc;
        *(float4*)&out[((bb * NHEAD + h) * SQ + srow) * HDIM + tx * 4] = o;
    }
}

// ---------------------------------------------------------------------------
// TF32 mma helpers
// ---------------------------------------------------------------------------
__device__ __forceinline__ unsigned f2tf(float x) {
    unsigned r;
    asm("cvt.rna.tf32.f32 %0, %1;" : "=r"(r) : "f"(x));
    return r;
}
__device__ __forceinline__ float f2tff(float x) {
    return __uint_as_float(f2tf(x));
}
__device__ __forceinline__ void mma_tf32(float c[4], const unsigned a[4],
                                         unsigned b0, unsigned b1) {
    asm volatile(
        "mma.sync.aligned.m16n8k8.row.col.f32.tf32.tf32.f32 "
        "{%0,%1,%2,%3}, {%4,%5,%6,%7}, {%8,%9}, {%0,%1,%2,%3};"
        : "+f"(c[0]), "+f"(c[1]), "+f"(c[2]), "+f"(c[3])
        : "r"(a[0]), "r"(a[1]), "r"(a[2]), "r"(a[3]), "r"(b0), "r"(b1));
}

// ---------------------------------------------------------------------------
// Kernel 2: flash attention, TF32 tensor cores.
// grid = (SQ/64, B*NH); block = 128 (4 warps, m16 q-rows per warp)
// smem: Ks[64][68] K[j][d] | Vt[64][68] V^T[d][j] | Ps[64][68] P[q][j]
// ---------------------------------------------------------------------------
#define STR 68
#define ATTN_SMEM (3 * 64 * STR * (int)sizeof(float))

__global__ __launch_bounds__(128)
void attn_kernel(const float* __restrict__ kvs,
                 const float* __restrict__ kvw_p,
                 float* __restrict__ out)
{
    extern __shared__ float sm[];
    float* Ks = sm;                   // [j][d]
    float* Vt = sm + 64 * STR;        // [d][j]
    float* Ps = sm + 2 * 64 * STR;    // [q][j]

    const int tid  = threadIdx.x;
    const int lane = tid & 31;
    const int w    = tid >> 5;
    const int r0   = lane >> 2;       // 0..7
    const int m4   = lane & 3;        // 0..3
    const int wq   = w * 16;          // warp's q-row base within CTA tile

    const int q0 = blockIdx.x * 64;
    const int bh = blockIdx.y;
    const int bb = bh >> 4, h = bh & 15;
    const float kvw = kvw_p[0];

    // ---- Q fragments (stay in registers for all 64 key tiles) ----
    unsigned qa[8][4];
    {
        const float* qb = g_q + ((size_t)bh * SQ + q0 + wq) * HDIM;
        #pragma unroll
        for (int kk = 0; kk < 8; kk++) {
            qa[kk][0] = f2tf(qb[(r0    ) * HDIM + kk * 8 + m4    ]);
            qa[kk][1] = f2tf(qb[(r0 + 8) * HDIM + kk * 8 + m4    ]);
            qa[kk][2] = f2tf(qb[(r0    ) * HDIM + kk * 8 + m4 + 4]);
            qa[kk][3] = f2tf(qb[(r0 + 8) * HDIM + kk * 8 + m4 + 4]);
        }
    }

    float oacc[8][4] = {};
    float mrun[2] = {-INFINITY, -INFINITY};
    float lrun[2] = {0.0f, 0.0f};

    const int   jrow  = tid >> 1;          // 0..63 : row this thread loads
    const int   dbase = (tid & 1) * 32;

    const float* kb0 = kvs + (size_t)bh * SKVLEN * HDIM;
    const float* vb0 = kvs + ((size_t)NB * NHEAD + bh) * SKVLEN * HDIM;
    const float* kb1 = g_k + (size_t)bh * SQ * HDIM;
    const float* vb1 = g_v + (size_t)bh * SQ * HDIM;

    for (int kt = 0; kt < TKV / 64; kt++) {
        // ---- stage K/V tile into smem (scaled, tf32-rounded) ----
        int jg = kt * 64 + jrow;
        const float *kp, *vp;
        float wj;
        if (jg < SKVLEN) { kp = kb0 + (size_t)jg * HDIM; vp = vb0 + (size_t)jg * HDIM; wj = kvw; }
        else { int js = jg - SKVLEN; kp = kb1 + (size_t)js * HDIM; vp = vb1 + (size_t)js * HDIM; wj = 1.0f; }

        __syncthreads();   // previous step's mma reads of Ks/Vt complete
        #pragma unroll
        for (int i = 0; i < 8; i++) {
            int d0 = dbase + i * 4;
            float4 kf = *(const float4*)(kp + d0);
            Ks[jrow * STR + d0 + 0] = f2tff(kf.x * wj);
            Ks[jrow * STR + d0 + 1] = f2tff(kf.y * wj);
            Ks[jrow * STR + d0 + 2] = f2tff(kf.z * wj);
            Ks[jrow * STR + d0 + 3] = f2tff(kf.w * wj);
            float4 vf = *(const float4*)(vp + d0);
            Vt[(d0 + 0) * STR + jrow] = f2tff(vf.x * wj);
            Vt[(d0 + 1) * STR + jrow] = f2tff(vf.y * wj);
            Vt[(d0 + 2) * STR + jrow] = f2tff(vf.z * wj);
            Vt[(d0 + 3) * STR + jrow] = f2tff(vf.w * wj);
        }
        __syncthreads();

        // ---- GEMM1: S = Q K^T  (m16 x n64, k=64) ----
        float sc[8][4] = {};
        #pragma unroll
        for (int kk = 0; kk < 8; kk++) {
            #pragma unroll
            for (int nb = 0; nb < 8; nb++) {
                const float* kr = &Ks[(nb * 8 + r0) * STR + kk * 8 + m4];
                unsigned b0 = __float_as_uint(kr[0]);
                unsigned b1 = __float_as_uint(kr[4]);
                mma_tf32(sc[nb], qa[kk], b0, b1);
            }
        }

        // ---- online softmax (2 rows per thread, quad reduce) ----
        float alpha[2];
        #pragma unroll
        for (int r = 0; r < 2; r++) {
            float mv = -INFINITY;
            #pragma unroll
            for (int nb = 0; nb < 8; nb++)
                mv = fmaxf(mv, fmaxf(sc[nb][2 * r], sc[nb][2 * r + 1]));
            mv = fmaxf(mv, __shfl_xor_sync(0xffffffffu, mv, 1));
            mv = fmaxf(mv, __shfl_xor_sync(0xffffffffu, mv, 2));
            float mn = fmaxf(mrun[r], mv);
            alpha[r] = __expf(mrun[r] - mn);
            mrun[r] = mn;
            float s = 0.0f;
            #pragma unroll
            for (int nb = 0; nb < 8; nb++) {
                sc[nb][2 * r]     = __expf(sc[nb][2 * r]     - mn);
                sc[nb][2 * r + 1] = __expf(sc[nb][2 * r + 1] - mn);
                s += sc[nb][2 * r] + sc[nb][2 * r + 1];
            }
            s += __shfl_xor_sync(0xffffffffu, s, 1);
            s += __shfl_xor_sync(0xffffffffu, s, 2);
            lrun[r] = lrun[r] * alpha[r] + s;
            #pragma unroll
            for (int nb = 0; nb < 8; nb++) {
                oacc[nb][2 * r]     *= alpha[r];
                oacc[nb][2 * r + 1] *= alpha[r];
            }
        }

        // ---- store P (warp-private rows), tf32-rounded ----
        float* pw = Ps + wq * STR;
        #pragma unroll
        for (int nb = 0; nb < 8; nb++) {
            float2 p0 = {f2tff(sc[nb][0]), f2tff(sc[nb][1])};
            float2 p1 = {f2tff(sc[nb][2]), f2tff(sc[nb][3])};
            *(float2*)&pw[(r0    ) * STR + nb * 8 + 2 * m4] = p0;
            *(float2*)&pw[(r0 + 8) * STR + nb * 8 + 2 * m4] = p1;
        }
        __syncwarp();

        // ---- GEMM2: O += P V  (m16 x n64, k=64) ----
        #pragma unroll
        for (int kk = 0; kk < 8; kk++) {
            unsigned pa[4];
            pa[0] = __float_as_uint(pw[(r0    ) * STR + kk * 8 + m4    ]);
            pa[1] = __float_as_uint(pw[(r0 + 8) * STR + kk * 8 + m4    ]);
            pa[2] = __float_as_uint(pw[(r0    ) * STR + kk * 8 + m4 + 4]);
            pa[3] = __float_as_uint(pw[(r0 + 8) * STR + kk * 8 + m4 + 4]);
            #pragma unroll
            for (int nb = 0; nb < 8; nb++) {
                const float* vr = &Vt[(nb * 8 + r0) * STR + kk * 8 + m4];
                unsigned b0 = __float_as_uint(vr[0]);
                unsigned b1 = __float_as_uint(vr[4]);
                mma_tf32(oacc[nb], pa, b0, b1);
            }
        }
    }

    // ---- epilogue ----
    float inv0 = 1.0f / lrun[0];
    float inv1 = 1.0f / lrun[1];
    float* ob = out + ((size_t)(bb * SQ + q0 + wq)) * HIDDEN + h * HDIM;
    #pragma unroll
    for (int nb = 0; nb < 8; nb++) {
        float2 v0 = {oacc[nb][0] * inv0, oacc[nb][1] * inv0};
        float2 v1 = {oacc[nb][2] * inv1, oacc[nb][3] * inv1};
        *(float2*)&ob[(r0    ) * HIDDEN + nb * 8 + 2 * m4] = v0;
        *(float2*)&ob[(r0 + 8) * HIDDEN + nb * 8 + 2 * m4] = v1;
    }
}

// ---------------------------------------------------------------------------
extern "C" void kernel_launch(void* const* d_in, const int* in_sizes, int n_in,
                              void* d_out, int out_size)
{
    const float* x    = (const float*)d_in[0];
    const float* kvs  = (const float*)d_in[1];
    const float* Wq   = (const float*)d_in[2];
    const float* bq   = (const float*)d_in[3];
    const float* Wk   = (const float*)d_in[4];
    const float* bk   = (const float*)d_in[5];
    const float* Wv   = (const float*)d_in[6];
    const float* bv   = (const float*)d_in[7];
    const float* kvw  = (const float*)d_in[8];
    float* out = (float*)d_out;

    dim3 g1(NB * SQ / 64, HIDDEN / 64, 3);
    qkv_kernel<<<g1, 256>>>(x, Wq, bq, Wk, bk, Wv, bv);

    cudaFuncSetAttribute(attn_kernel, cudaFuncAttributeMaxDynamicSharedMemorySize,
                         ATTN_SMEM);
    dim3 g2(SQ / 64, NB * NHEAD);
    attn_kernel<<<g2, 256 / 2, ATTN_SMEM>>>(kvs, kvw, out);
}

// round 3
// speedup vs baseline: 7.0067x; 4.7269x over previous
#include <cuda_runtime.h>
#include <cuda_fp16.h>
#include <math.h>

#define NB     2
#define SQ     2048
#define HIDDEN 1024
#define NHEAD  16
#define HDIM   64
#define SKVLEN 2048
#define TKV    4096

// half-precision staging buffers
__device__ __half d_xh[NB * SQ * HIDDEN];
__device__ __half d_wh[3 * HIDDEN * HIDDEN];
__device__ __half d_kvsh[2 * NB * NHEAD * SKVLEN * HDIM];
__device__ __half d_qh[NB * NHEAD * SQ * HDIM];   // pre-scaled by 1/64
__device__ __half d_kh[NB * NHEAD * SQ * HDIM];
__device__ __half d_vh[NB * NHEAD * SQ * HDIM];

// ---------------------------------------------------------------------------
// helpers
// ---------------------------------------------------------------------------
__device__ __forceinline__ void mma16816(float c[4], unsigned a0, unsigned a1,
                                         unsigned a2, unsigned a3,
                                         unsigned b0, unsigned b1) {
    asm volatile(
        "mma.sync.aligned.m16n8k16.row.col.f32.f16.f16.f32 "
        "{%0,%1,%2,%3},{%4,%5,%6,%7},{%8,%9},{%0,%1,%2,%3};"
        : "+f"(c[0]), "+f"(c[1]), "+f"(c[2]), "+f"(c[3])
        : "r"(a0), "r"(a1), "r"(a2), "r"(a3), "r"(b0), "r"(b1));
}
__device__ __forceinline__ void ldsm_x4(unsigned& r0, unsigned& r1,
                                        unsigned& r2, unsigned& r3, unsigned a) {
    asm volatile("ldmatrix.sync.aligned.m8n8.x4.shared.b16 {%0,%1,%2,%3},[%4];"
                 : "=r"(r0), "=r"(r1), "=r"(r2), "=r"(r3) : "r"(a));
}
__device__ __forceinline__ void ldsm_x4t(unsigned& r0, unsigned& r1,
                                         unsigned& r2, unsigned& r3, unsigned a) {
    asm volatile("ldmatrix.sync.aligned.m8n8.x4.trans.shared.b16 {%0,%1,%2,%3},[%4];"
                 : "=r"(r0), "=r"(r1), "=r"(r2), "=r"(r3) : "r"(a));
}
__device__ __forceinline__ void cp16(unsigned saddr, const void* g) {
    asm volatile("cp.async.cg.shared.global [%0],[%1],16;" :: "r"(saddr), "l"(g));
}
__device__ __forceinline__ void cp_commit() {
    asm volatile("cp.async.commit_group;" ::: "memory");
}
__device__ __forceinline__ void cp_wait0() {
    asm volatile("cp.async.wait_group 0;" ::: "memory");
}
__device__ __forceinline__ unsigned pack_h2(float lo, float hi) {
    __half2 h = __floats2half2_rn(lo, hi);
    return *reinterpret_cast<unsigned*>(&h);
}

// ---------------------------------------------------------------------------
// fp32 -> fp16 conversion (optionally scaled by *sp)
// ---------------------------------------------------------------------------
__global__ void cvt_kernel(const float* __restrict__ src, __half2* __restrict__ dst,
                           int n4, const float* __restrict__ sp) {
    int i = blockIdx.x * blockDim.x + threadIdx.x;
    if (i >= n4) return;
    float s = sp ? sp[0] : 1.0f;
    float4 v = reinterpret_cast<const float4*>(src)[i];
    dst[2 * i]     = __floats2half2_rn(v.x * s, v.y * s);
    dst[2 * i + 1] = __floats2half2_rn(v.z * s, v.w * s);
}

// ---------------------------------------------------------------------------
// QKV projection: y = x @ W^T + b, fp16 mma, fp32 accum.
// grid = (64, 16, 3), block = 128 (4 warps x 16 m-rows), kstep = 32.
// ---------------------------------------------------------------------------
__global__ __launch_bounds__(128)
void qkv_kernel(const float* __restrict__ bq, const float* __restrict__ bk,
                const float* __restrict__ bv)
{
    __shared__ __align__(16) __half sAB[2 * 2 * 64 * 40];

    const int z = blockIdx.z;
    const __half* __restrict__ W = d_wh + (size_t)z * HIDDEN * HIDDEN;
    const float* __restrict__ bias = (z == 0) ? bq : (z == 1) ? bk : bv;
    __half* __restrict__ outp = (z == 0) ? d_qh : (z == 1) ? d_kh : d_vh;
    const float scl = (z == 0) ? (1.0f / 64.0f) : 1.0f;

    const int m0 = blockIdx.x * 64;
    const int h  = blockIdx.y;
    const int n0 = h * 64;
    const int tid = threadIdx.x, lane = tid & 31, w = tid >> 5;
    const int wq16 = w * 16;
    const int l = lane;

    const unsigned sbase = (unsigned)__cvta_generic_to_shared(sAB);
    const unsigned aoffB = sbase + 2 * ((((l & 7) + ((l >> 3) & 1) * 8) + wq16) * 40 + (l >> 4) * 8);
    const unsigned boffB = sbase + 5120 + 2 * (((l >> 4) * 8 + (l & 7)) * 40 + ((l >> 3) & 1) * 8);

    const int srow = tid >> 2;        // 0..31 (per-u +32)
    const int sc4  = tid & 3;

    auto issue = [&](int ks, int buf) {
        int k0 = ks * 32;
        #pragma unroll
        for (int u = 0; u < 2; u++) {
            int row = srow + u * 32;
            unsigned dA = sbase + buf * 10240 + (row * 40 + sc4 * 8) * 2;
            cp16(dA, d_xh + (size_t)(m0 + row) * HIDDEN + k0 + sc4 * 8);
            cp16(dA + 5120, W + (size_t)(n0 + row) * HIDDEN + k0 + sc4 * 8);
        }
    };

    float acc[8][4] = {};

    issue(0, 0);
    cp_commit();

    for (int ks = 0; ks < 32; ks++) {
        int buf = ks & 1;
        cp_wait0();
        __syncthreads();
        if (ks < 31) { issue(ks + 1, buf ^ 1); cp_commit(); }

        unsigned bo = buf * 10240;
        #pragma unroll
        for (int kb = 0; kb < 2; kb++) {
            unsigned a0, a1, a2, a3;
            ldsm_x4(a0, a1, a2, a3, aoffB + bo + kb * 32);
            #pragma unroll
            for (int nbp = 0; nbp < 4; nbp++) {
                unsigned b0, b1, b2, b3;
                ldsm_x4(b0, b1, b2, b3, boffB + bo + nbp * 1280 + kb * 32);
                mma16816(acc[nbp * 2],     a0, a1, a2, a3, b0, b1);
                mma16816(acc[nbp * 2 + 1], a0, a1, a2, a3, b2, b3);
            }
        }
        __syncthreads();
    }

    // epilogue: bias, scale, convert, store to [b][h][s][d] half layout
    const int mlo = m0 + wq16 + (lane >> 2);
    #pragma unroll
    for (int nb = 0; nb < 8; nb++) {
        int dcol = nb * 8 + 2 * (lane & 3);
        float2 bv2 = *(const float2*)&bias[n0 + dcol];
        __half2 h0 = __floats2half2_rn((acc[nb][0] + bv2.x) * scl,
                                       (acc[nb][1] + bv2.y) * scl);
        __half2 h1 = __floats2half2_rn((acc[nb][2] + bv2.x) * scl,
                                       (acc[nb][3] + bv2.y) * scl);
        int m1 = mlo, m2 = mlo + 8;
        *(__half2*)&outp[(((size_t)(m1 >> 11) * NHEAD + h) * SQ + (m1 & 2047)) * HDIM + dcol] = h0;
        *(__half2*)&outp[(((size_t)(m2 >> 11) * NHEAD + h) * SQ + (m2 & 2047)) * HDIM + dcol] = h1;
    }
}

// ---------------------------------------------------------------------------
// Flash attention, fp16 mma, register-resident P, cp.async double buffer.
// grid = (32, 32), block = 128 (4 warps x 16 q-rows).
// smem: [buf][ K[64][72] | V[64][72] ] halves.
// ---------------------------------------------------------------------------
__global__ __launch_bounds__(128)
void attn_kernel(float* __restrict__ out)
{
    __shared__ __align__(16) __half sKV[2 * 2 * 64 * 72];

    const int tid = threadIdx.x, lane = tid & 31, w = tid >> 5;
    const int r0 = lane >> 2, m4 = lane & 3;
    const int wq = w * 16;
    const int q0 = blockIdx.x * 64;
    const int bh = blockIdx.y, bb = bh >> 4, h = bh & 15;
    const int l = lane;

    const unsigned sbase = (unsigned)__cvta_generic_to_shared(sKV);
    const unsigned koffB = sbase + 2 * (((l >> 4) * 8 + (l & 7)) * 72 + ((l >> 3) & 1) * 8);
    const unsigned voffB = sbase + 9216 + 2 * ((((l >> 3) & 1) * 8 + (l & 7)) * 72 + (l >> 4) * 8);
    const unsigned ONES = 0x3C003C00u;

    // Q fragments, resident for whole kernel
    unsigned qa[4][4];
    {
        const __half* qb = d_qh + ((size_t)bh * SQ + q0 + wq) * HDIM;
        #pragma unroll
        for (int kb = 0; kb < 4; kb++) {
            qa[kb][0] = *(const unsigned*)&qb[(r0    ) * 64 + kb * 16 + 2 * m4    ];
            qa[kb][1] = *(const unsigned*)&qb[(r0 + 8) * 64 + kb * 16 + 2 * m4    ];
            qa[kb][2] = *(const unsigned*)&qb[(r0    ) * 64 + kb * 16 + 2 * m4 + 8];
            qa[kb][3] = *(const unsigned*)&qb[(r0 + 8) * 64 + kb * 16 + 2 * m4 + 8];
        }
    }

    float oacc[8][4] = {};
    float mrun[2] = {-INFINITY, -INFINITY};
    float lrun[2] = {0.0f, 0.0f};

    const __half* kB0 = d_kvsh + (size_t)bh * SKVLEN * HDIM;
    const __half* vB0 = d_kvsh + ((size_t)(NB * NHEAD) + bh) * SKVLEN * HDIM;
    const __half* kB1 = d_kh + (size_t)bh * SQ * HDIM;
    const __half* vB1 = d_vh + (size_t)bh * SQ * HDIM;

    auto issue = [&](int kt, int buf) {
        int jg0 = kt * 64;
        const __half *ks, *vs;
        if (jg0 < SKVLEN) { ks = kB0 + (size_t)jg0 * HDIM; vs = vB0 + (size_t)jg0 * HDIM; }
        else { int js = jg0 - SKVLEN; ks = kB1 + (size_t)js * HDIM; vs = vB1 + (size_t)js * HDIM; }
        #pragma unroll
        for (int u = 0; u < 4; u++) {
            int idx = tid + u * 128;
            int row = idx >> 3, c8 = idx & 7;
            unsigned dK = sbase + buf * 18432 + (row * 72 + c8 * 8) * 2;
            cp16(dK,        ks + row * 64 + c8 * 8);
            cp16(dK + 9216, vs + row * 64 + c8 * 8);
        }
    };

    issue(0, 0);
    cp_commit();

    for (int kt = 0; kt < TKV / 64; kt++) {
        int buf = kt & 1;
        cp_wait0();
        __syncthreads();
        if (kt < TKV / 64 - 1) { issue(kt + 1, buf ^ 1); cp_commit(); }
        unsigned bo = buf * 18432;

        // ---- GEMM1: S = Q K^T ----
        float scf[8][4] = {};
        #pragma unroll
        for (int kb = 0; kb < 4; kb++) {
            #pragma unroll
            for (int nbp = 0; nbp < 4; nbp++) {
                unsigned b0, b1, b2, b3;
                ldsm_x4(b0, b1, b2, b3, koffB + bo + nbp * 2304 + kb * 32);
                mma16816(scf[nbp * 2],     qa[kb][0], qa[kb][1], qa[kb][2], qa[kb][3], b0, b1);
                mma16816(scf[nbp * 2 + 1], qa[kb][0], qa[kb][1], qa[kb][2], qa[kb][3], b2, b3);
            }
        }

        // ---- online softmax ----
        float alpha[2], mn[2];
        #pragma unroll
        for (int r = 0; r < 2; r++) {
            float mv = -INFINITY;
            #pragma unroll
            for (int nb = 0; nb < 8; nb++)
                mv = fmaxf(mv, fmaxf(scf[nb][2 * r], scf[nb][2 * r + 1]));
            mv = fmaxf(mv, __shfl_xor_sync(0xffffffffu, mv, 1));
            mv = fmaxf(mv, __shfl_xor_sync(0xffffffffu, mv, 2));
            mn[r] = fmaxf(mrun[r], mv);
            alpha[r] = __expf(mrun[r] - mn[r]);
            mrun[r] = mn[r];
            #pragma unroll
            for (int nb = 0; nb < 8; nb++) {
                oacc[nb][2 * r]     *= alpha[r];
                oacc[nb][2 * r + 1] *= alpha[r];
            }
        }

        // P fragments (exp in fp32, packed to half2; A-layout = C-layout trick)
        unsigned pa[4][4];
        #pragma unroll
        for (int kb = 0; kb < 4; kb++) {
            int nb0 = 2 * kb, nb1 = 2 * kb + 1;
            pa[kb][0] = pack_h2(__expf(scf[nb0][0] - mn[0]), __expf(scf[nb0][1] - mn[0]));
            pa[kb][1] = pack_h2(__expf(scf[nb0][2] - mn[1]), __expf(scf[nb0][3] - mn[1]));
            pa[kb][2] = pack_h2(__expf(scf[nb1][0] - mn[0]), __expf(scf[nb1][1] - mn[0]));
            pa[kb][3] = pack_h2(__expf(scf[nb1][2] - mn[1]), __expf(scf[nb1][3] - mn[1]));
        }

        // ---- GEMM2: O += P V, plus P row-sums via ones-B mma ----
        float ls[4] = {0.0f, 0.0f, 0.0f, 0.0f};
        #pragma unroll
        for (int kb = 0; kb < 4; kb++) {
            mma16816(ls, pa[kb][0], pa[kb][1], pa[kb][2], pa[kb][3], ONES, ONES);
            #pragma unroll
            for (int nbp = 0; nbp < 4; nbp++) {
                unsigned b0, b1, b2, b3;
                ldsm_x4t(b0, b1, b2, b3, voffB + bo + kb * 2304 + nbp * 32);
                mma16816(oacc[nbp * 2],     pa[kb][0], pa[kb][1], pa[kb][2], pa[kb][3], b0, b1);
                mma16816(oacc[nbp * 2 + 1], pa[kb][0], pa[kb][1], pa[kb][2], pa[kb][3], b2, b3);
            }
        }
        lrun[0] = lrun[0] * alpha[0] + ls[0];
        lrun[1] = lrun[1] * alpha[1] + ls[2];
        __syncthreads();
    }

    // ---- epilogue ----
    float inv0 = 1.0f / lrun[0];
    float inv1 = 1.0f / lrun[1];
    float* ob = out + ((size_t)(bb * SQ + q0 + wq)) * HIDDEN + h * HDIM;
    #pragma unroll
    for (int nb = 0; nb < 8; nb++) {
        float2 v0 = {oacc[nb][0] * inv0, oacc[nb][1] * inv0};
        float2 v1 = {oacc[nb][2] * inv1, oacc[nb][3] * inv1};
        *(float2*)&ob[(r0    ) * HIDDEN + nb * 8 + 2 * m4] = v0;
        *(float2*)&ob[(r0 + 8) * HIDDEN + nb * 8 + 2 * m4] = v1;
    }
}

// ---------------------------------------------------------------------------
extern "C" void kernel_launch(void* const* d_in, const int* in_sizes, int n_in,
                              void* d_out, int out_size)
{
    const float* x    = (const float*)d_in[0];
    const float* kvs  = (const float*)d_in[1];
    const float* Wq   = (const float*)d_in[2];
    const float* bq   = (const float*)d_in[3];
    const float* Wk   = (const float*)d_in[4];
    const float* bk   = (const float*)d_in[5];
    const float* Wv   = (const float*)d_in[6];
    const float* bv   = (const float*)d_in[7];
    const float* kvw  = (const float*)d_in[8];
    float* out = (float*)d_out;

    void *p_xh, *p_wh, *p_kvsh;
    cudaGetSymbolAddress(&p_xh, d_xh);
    cudaGetSymbolAddress(&p_wh, d_wh);
    cudaGetSymbolAddress(&p_kvsh, d_kvsh);
    __half2* xh2   = (__half2*)p_xh;
    __half*  wh    = (__half*)p_wh;
    __half2* kvsh2 = (__half2*)p_kvsh;

    const int WN4 = HIDDEN * HIDDEN / 4;
    cvt_kernel<<<(NB * SQ * HIDDEN / 4 + 255) / 256, 256>>>(x, xh2, NB * SQ * HIDDEN / 4, nullptr);
    cvt_kernel<<<(WN4 + 255) / 256, 256>>>(Wq, (__half2*)(wh),                NB ? WN4 : 0, nullptr);
    cvt_kernel<<<(WN4 + 255) / 256, 256>>>(Wk, (__half2*)(wh + HIDDEN * HIDDEN),     WN4, nullptr);
    cvt_kernel<<<(WN4 + 255) / 256, 256>>>(Wv, (__half2*)(wh + 2 * HIDDEN * HIDDEN), WN4, nullptr);
    cvt_kernel<<<(2 * NB * NHEAD * SKVLEN * HDIM / 4 + 255) / 256, 256>>>(
        kvs, kvsh2, 2 * NB * NHEAD * SKVLEN * HDIM / 4, kvw);

    dim3 g1(NB * SQ / 64, NHEAD, 3);
    qkv_kernel<<<g1, 128>>>(bq, bk, bv);

    dim3 g2(SQ / 64, NB * NHEAD);
    attn_kernel<<<g2, 128>>>(out);
}